// round 10
// baseline (speedup 1.0000x reference)
#include <cuda_runtime.h>
#include <cuda_fp16.h>
#include <cstdint>

#define TT    8192
#define OBSN  512
#define HIDN  2048
#define NOBJN 8
#define CH    64
#define NCH   128   // TT / CH

#define SCL  2048.0f
#define ISCL (1.0f / 2048.0f)

// ---------------- scratch (device globals; no allocation allowed) ----------
__device__ float g_Abar[TT * HIDN];
__device__ float g_Bx  [TT * HIDN];
__device__ float g_C   [TT * HIDN];
__device__ float g_y   [TT * HIDN];
__device__ float g_P    [NCH * HIDN];
__device__ float g_E    [NCH * HIDN];
__device__ float g_carry[NCH * HIDN];

// fp16 split copies (lo pre-scaled by 2^11)
__device__ __half g_xh[TT * OBSN];
__device__ __half g_xl[TT * OBSN];
__device__ __half g_wh[4 * HIDN * OBSN];
__device__ __half g_wl[4 * HIDN * OBSN];

// ---------------- helpers ---------------------------------------------------
__device__ __forceinline__ uint32_t smem_u32(const void* p) {
    uint32_t a;
    asm("{ .reg .u64 t; cvta.to.shared.u64 t, %1; cvt.u32.u64 %0, t; }"
        : "=r"(a) : "l"(p));
    return a;
}

__device__ __forceinline__ void cp16(uint32_t dst, const void* src) {
    asm volatile("cp.async.cg.shared.global [%0], [%1], 16;"
                 :: "r"(dst), "l"(src) : "memory");
}
#define CP_COMMIT() asm volatile("cp.async.commit_group;" ::: "memory")
#define CP_WAIT(n)  asm volatile("cp.async.wait_group %0;" :: "n"(n) : "memory")

__device__ __forceinline__ void ldm_x4(uint32_t* r, uint32_t addr) {
    asm volatile("ldmatrix.sync.aligned.m8n8.x4.shared.b16 {%0,%1,%2,%3}, [%4];"
                 : "=r"(r[0]), "=r"(r[1]), "=r"(r[2]), "=r"(r[3]) : "r"(addr));
}

// main term: fp16 inputs, fp32 accumulate
__device__ __forceinline__ void mma_f32acc(float* c, const uint32_t* a,
                                           const uint32_t* b) {
    asm volatile(
        "mma.sync.aligned.m16n8k16.row.col.f32.f16.f16.f32 "
        "{%0,%1,%2,%3}, {%4,%5,%6,%7}, {%8,%9}, {%0,%1,%2,%3};"
        : "+f"(c[0]), "+f"(c[1]), "+f"(c[2]), "+f"(c[3])
        : "r"(a[0]), "r"(a[1]), "r"(a[2]), "r"(a[3]), "r"(b[0]), "r"(b[1]));
}

// correction terms: fp16 inputs, fp16 accumulate (2 packed-b32 accumulator)
__device__ __forceinline__ void mma_f16acc(uint32_t* c, const uint32_t* a,
                                           const uint32_t* b) {
    asm volatile(
        "mma.sync.aligned.m16n8k16.row.col.f16.f16.f16.f16 "
        "{%0,%1}, {%2,%3,%4,%5}, {%6,%7}, {%0,%1};"
        : "+r"(c[0]), "+r"(c[1])
        : "r"(a[0]), "r"(a[1]), "r"(a[2]), "r"(a[3]), "r"(b[0]), "r"(b[1]));
}

// conflict-free swizzle: rows are 64B; 8 consecutive rows hit 8 distinct
// 16B slots mod 128B
__device__ __forceinline__ uint32_t swz(int row, int c16) {
    return (uint32_t)(row * 64 + (((c16 ^ (row >> 1)) & 3) << 4));
}

// ---------------- K0: fp32 -> (fp16 hi, fp16 lo*2^11) split ----------------
__global__ __launch_bounds__(256)
void split_kernel(const float* __restrict__ src,
                  __half* __restrict__ hi,
                  __half* __restrict__ lo, int n4)
{
    int i = blockIdx.x * 256 + threadIdx.x;
    if (i >= n4) return;
    float4 v = ((const float4*)src)[i];
    __half h0 = __float2half(v.x);
    __half h1 = __float2half(v.y);
    __half h2 = __float2half(v.z);
    __half h3 = __float2half(v.w);
    __half2* hp = (__half2*)hi;
    __half2* lp = (__half2*)lo;
    hp[i * 2 + 0] = __half2(h0, h1);
    hp[i * 2 + 1] = __half2(h2, h3);
    lp[i * 2 + 0] = __half2(__float2half((v.x - __half2float(h0)) * SCL),
                            __float2half((v.y - __half2float(h1)) * SCL));
    lp[i * 2 + 1] = __half2(__float2half((v.z - __half2float(h2)) * SCL),
                            __float2half((v.w - __half2float(h3)) * SCL));
}

__global__ __launch_bounds__(256)
void splitw_kernel(const float* __restrict__ w0, const float* __restrict__ w1,
                   const float* __restrict__ w2, const float* __restrict__ w3)
{
    const float* src[4] = {w0, w1, w2, w3};
    int mm = blockIdx.y;
    int n4 = HIDN * OBSN / 4;
    int i = blockIdx.x * 256 + threadIdx.x;
    if (i >= n4) return;
    float4 v = ((const float4*)src[mm])[i];
    size_t off = (size_t)mm * (HIDN * OBSN / 2);
    __half2* hp = (__half2*)g_wh + off;
    __half2* lp = (__half2*)g_wl + off;
    __half h0 = __float2half(v.x);
    __half h1 = __float2half(v.y);
    __half h2 = __float2half(v.z);
    __half h3 = __float2half(v.w);
    hp[i * 2 + 0] = __half2(h0, h1);
    hp[i * 2 + 1] = __half2(h2, h3);
    lp[i * 2 + 0] = __half2(__float2half((v.x - __half2float(h0)) * SCL),
                            __float2half((v.y - __half2float(h1)) * SCL));
    lp[i * 2 + 1] = __half2(__float2half((v.z - __half2float(h2)) * SCL),
                            __float2half((v.w - __half2float(h3)) * SCL));
}

// ---------------- K1: fused 4-projection GEMM, fp16 main + f16-acc corr ----
// 512 threads. Warps 0-7: main term (f32 acc), task (m, mh).
// Warps 8-15: both correction terms into one f16 accumulator, task (m, mh).
#define PM 128
#define PN 32
#define KC 32
#define NKC (OBSN / KC)           // 16
#define X_TILE_B   8192           // 128*32*2
#define W_TILE_B   2048           // 32*32*2
#define STAGE_B    32768          // 2*X + 8*W
#define NSTAGE 3
#define PROJ_SMEM  (NSTAGE * STAGE_B)  // 96KB

// epilogue smem layout (floats)
#define CBS  33                   // corr buffer stride
#define CB_MAT (128 * CBS)        // per-matrix corr area
#define SF_OFF (4 * CB_MAT)       // x_state exchange after corr buffers
#define ES   36

__global__ __launch_bounds__(512, 1)
void proj_mma_kernel(const float* __restrict__ Alog)
{
    extern __shared__ char smem[];
    const uint32_t sbase = smem_u32(smem);
    const int tid  = threadIdx.x;
    const int wid  = tid >> 5;
    const int lane = tid & 31;
    const int t0   = blockIdx.y * PM;
    const int h0   = blockIdx.x * PN;
    const int role = wid >> 3;      // 0 = main, 1 = corrections
    const int task = wid & 7;
    const int m    = task & 3;      // matrix index
    const int mh   = task >> 2;     // M-half

    float    accm[4][4][4];         // main (role 0)
    uint32_t accc[4][4][2];         // corrections, packed f16x2 (role 1)
#pragma unroll
    for (int i = 0; i < 4; i++)
#pragma unroll
        for (int j = 0; j < 4; j++) {
#pragma unroll
            for (int k = 0; k < 4; k++) accm[i][j][k] = 0.f;
            accc[i][j][0] = 0u; accc[i][j][1] = 0u;
        }

    // ---- cp.async stage loader: 4 cp16 per thread (512 threads) ----
    auto issue = [&](int s) {
        if (s >= NKC) { CP_COMMIT(); return; }
        const uint32_t sb = sbase + (uint32_t)(s % NSTAGE) * STAGE_B;
        const int kel = s * KC;
        {   // x hi/lo: 512 chunks each -> 1 per thread per tile
            int row = tid >> 2, c16 = tid & 3;
            size_t gs = (size_t)(t0 + row) * OBSN + kel + c16 * 8;
            cp16(sb + swz(row, c16), g_xh + gs);
            cp16(sb + X_TILE_B + swz(row, c16), g_xl + gs);
        }
        {   // W: 8 tiles x 128 chunks = 1024 -> 2 per thread
            int id = tid & 127;
            int row = id >> 2, c16 = id & 3;
#pragma unroll
            for (int j = 0; j < 2; j++) {
                int tl  = (tid >> 7) + j * 4;     // 0..7
                int var = tl >> 2, mm = tl & 3;
                const __half* base = var ? g_wl : g_wh;
                size_t gs = ((size_t)mm * HIDN + h0 + row) * OBSN + kel + c16 * 8;
                cp16(sb + 2 * X_TILE_B + (var * 4 + mm) * W_TILE_B + swz(row, c16),
                     base + gs);
            }
        }
        CP_COMMIT();
    };

    issue(0);
    issue(1);

    for (int s = 0; s < NKC; s++) {
        CP_WAIT(1);
        __syncthreads();
        issue(s + 2);

        const uint32_t sb   = sbase + (uint32_t)(s % NSTAGE) * STAGE_B;
        const uint32_t xh_b = sb;
        const uint32_t xl_b = sb + X_TILE_B;
        const uint32_t wh_b = sb + 2 * X_TILE_B + m * W_TILE_B;
        const uint32_t wl_b = wh_b + 4 * W_TILE_B;

        if (role == 0) {
            // main: ah * bh, f32 accumulate
#pragma unroll
            for (int ks = 0; ks < 2; ks++) {
                uint32_t ah[4][4], bh[4][2];
#pragma unroll
                for (int mi = 0; mi < 4; mi++) {
                    int row = mh * 64 + mi * 16 + (lane & 15);
                    int c16 = ks * 2 + (lane >> 4);
                    ldm_x4(ah[mi], xh_b + swz(row, c16));
                }
#pragma unroll
                for (int np = 0; np < 2; np++) {
                    int row = np * 16 + (lane & 7) + ((lane >> 4) << 3);
                    int c16 = ks * 2 + ((lane >> 3) & 1);
                    uint32_t r[4];
                    ldm_x4(r, wh_b + swz(row, c16));
                    bh[2 * np][0] = r[0]; bh[2 * np][1] = r[1];
                    bh[2 * np + 1][0] = r[2]; bh[2 * np + 1][1] = r[3];
                }
#pragma unroll
                for (int mi = 0; mi < 4; mi++)
#pragma unroll
                    for (int nj = 0; nj < 4; nj++)
                        mma_f32acc(accm[mi][nj], ah[mi], bh[nj]);
            }
        } else {
            // corrections: ah*bl + al*bh, f16 accumulate
#pragma unroll
            for (int ks = 0; ks < 2; ks++) {
                uint32_t ah[4][4], al[4][4], bh[4][2], bl[4][2];
#pragma unroll
                for (int mi = 0; mi < 4; mi++) {
                    int row = mh * 64 + mi * 16 + (lane & 15);
                    int c16 = ks * 2 + (lane >> 4);
                    ldm_x4(ah[mi], xh_b + swz(row, c16));
                    ldm_x4(al[mi], xl_b + swz(row, c16));
                }
#pragma unroll
                for (int np = 0; np < 2; np++) {
                    int row = np * 16 + (lane & 7) + ((lane >> 4) << 3);
                    int c16 = ks * 2 + ((lane >> 3) & 1);
                    uint32_t r[4];
                    ldm_x4(r, wh_b + swz(row, c16));
                    bh[2 * np][0] = r[0]; bh[2 * np][1] = r[1];
                    bh[2 * np + 1][0] = r[2]; bh[2 * np + 1][1] = r[3];
                    ldm_x4(r, wl_b + swz(row, c16));
                    bl[2 * np][0] = r[0]; bl[2 * np][1] = r[1];
                    bl[2 * np + 1][0] = r[2]; bl[2 * np + 1][1] = r[3];
                }
#pragma unroll
                for (int mi = 0; mi < 4; mi++)
#pragma unroll
                    for (int nj = 0; nj < 4; nj++) {
                        mma_f16acc(accc[mi][nj], ah[mi], bl[nj]);
                        mma_f16acc(accc[mi][nj], al[mi], bh[nj]);
                    }
            }
        }
    }
    __syncthreads();   // all compute done; smem reusable

    float* sf = (float*)smem;
    const int rbase = mh * 64 + (lane >> 2);
    const int cbase = 2 * (lane & 3);

    // ---- corr warps: dump scaled corrections to smem ----
    if (role == 1) {
#pragma unroll
        for (int mi = 0; mi < 4; mi++)
#pragma unroll
            for (int nj = 0; nj < 4; nj++) {
                int r = rbase + mi * 16, c = nj * 8 + cbase;
                float2 f01 = __half22float2(
                    *reinterpret_cast<__half2*>(&accc[mi][nj][0]));
                float2 f23 = __half22float2(
                    *reinterpret_cast<__half2*>(&accc[mi][nj][1]));
                float* cb = sf + m * CB_MAT;
                cb[(r)     * CBS + c]     = f01.x * ISCL;
                cb[(r)     * CBS + c + 1] = f01.y * ISCL;
                cb[(r + 8) * CBS + c]     = f23.x * ISCL;
                cb[(r + 8) * CBS + c + 1] = f23.y * ISCL;
            }
    }
    __syncthreads();

    // ---- main warps: add corrections, compute epilogue ----
    if (role == 0) {
        const float* cb = sf + m * CB_MAT;
#pragma unroll
        for (int mi = 0; mi < 4; mi++)
#pragma unroll
            for (int nj = 0; nj < 4; nj++) {
                int r = rbase + mi * 16, c = nj * 8 + cbase;
                accm[mi][nj][0] += cb[(r)     * CBS + c];
                accm[mi][nj][1] += cb[(r)     * CBS + c + 1];
                accm[mi][nj][2] += cb[(r + 8) * CBS + c];
                accm[mi][nj][3] += cb[(r + 8) * CBS + c + 1];
            }

        if (m == 0) {   // x_state -> smem exchange区
            float* xs = sf + SF_OFF;
#pragma unroll
            for (int mi = 0; mi < 4; mi++)
#pragma unroll
                for (int nj = 0; nj < 4; nj++) {
                    int r = rbase + mi * 16, c = nj * 8 + cbase;
                    xs[(r)     * ES + c]     = accm[mi][nj][0];
                    xs[(r)     * ES + c + 1] = accm[mi][nj][1];
                    xs[(r + 8) * ES + c]     = accm[mi][nj][2];
                    xs[(r + 8) * ES + c + 1] = accm[mi][nj][3];
                }
        }
        if (m == 2) {   // C direct
#pragma unroll
            for (int mi = 0; mi < 4; mi++)
#pragma unroll
                for (int nj = 0; nj < 4; nj++) {
                    int r = rbase + mi * 16, c = nj * 8 + cbase;
                    size_t i0 = (size_t)(t0 + r) * HIDN + h0 + c;
                    size_t i1 = (size_t)(t0 + r + 8) * HIDN + h0 + c;
                    *(float2*)&g_C[i0] = make_float2(accm[mi][nj][0], accm[mi][nj][1]);
                    *(float2*)&g_C[i1] = make_float2(accm[mi][nj][2], accm[mi][nj][3]);
                }
        }
        if (m == 3) {   // delta -> A_bar
#pragma unroll
            for (int mi = 0; mi < 4; mi++)
#pragma unroll
                for (int nj = 0; nj < 4; nj++) {
                    int r = rbase + mi * 16, c = nj * 8 + cbase;
                    float aA0 = -expf(__ldg(&Alog[h0 + c]));
                    float aA1 = -expf(__ldg(&Alog[h0 + c + 1]));
                    float d0 = 1.f / (1.f + expf(-accm[mi][nj][0]));
                    float d1 = 1.f / (1.f + expf(-accm[mi][nj][1]));
                    float d2 = 1.f / (1.f + expf(-accm[mi][nj][2]));
                    float d3 = 1.f / (1.f + expf(-accm[mi][nj][3]));
                    size_t i0 = (size_t)(t0 + r) * HIDN + h0 + c;
                    size_t i1 = (size_t)(t0 + r + 8) * HIDN + h0 + c;
                    *(float2*)&g_Abar[i0] = make_float2(expf(d0 * aA0), expf(d1 * aA1));
                    *(float2*)&g_Abar[i1] = make_float2(expf(d2 * aA0), expf(d3 * aA1));
                }
        }
    }
    __syncthreads();
    if (role == 0 && m == 1) {   // B * x_state
        const float* xs = sf + SF_OFF;
#pragma unroll
        for (int mi = 0; mi < 4; mi++)
#pragma unroll
            for (int nj = 0; nj < 4; nj++) {
                int r = rbase + mi * 16, c = nj * 8 + cbase;
                float x0 = xs[(r)     * ES + c];
                float x1 = xs[(r)     * ES + c + 1];
                float x2 = xs[(r + 8) * ES + c];
                float x3 = xs[(r + 8) * ES + c + 1];
                size_t i0 = (size_t)(t0 + r) * HIDN + h0 + c;
                size_t i1 = (size_t)(t0 + r + 8) * HIDN + h0 + c;
                *(float2*)&g_Bx[i0] = make_float2(accm[mi][nj][0] * x0, accm[mi][nj][1] * x1);
                *(float2*)&g_Bx[i1] = make_float2(accm[mi][nj][2] * x2, accm[mi][nj][3] * x3);
            }
    }
}

// ---------------- K2: per-chunk scan (float2) -> (P, E) --------------------
__global__ __launch_bounds__(256)
void chunk_scan_kernel()
{
    int h2 = blockIdx.y * 256 + threadIdx.x;      // float2 column
    int c  = blockIdx.x;
    const float2* A2 = (const float2*)g_Abar;
    const float2* B2 = (const float2*)g_Bx;
    float2 P = make_float2(1.f, 1.f);
    float2 E = make_float2(0.f, 0.f);
    size_t base = (size_t)c * CH * (HIDN / 2) + h2;
#pragma unroll 4
    for (int i = 0; i < CH; i++) {
        float2 a  = A2[base + (size_t)i * (HIDN / 2)];
        float2 bx = B2[base + (size_t)i * (HIDN / 2)];
        E.x = a.x * E.x + bx.x;  E.y = a.y * E.y + bx.y;
        P.x *= a.x;  P.y *= a.y;
    }
    ((float2*)g_P)[(size_t)c * (HIDN / 2) + h2] = P;
    ((float2*)g_E)[(size_t)c * (HIDN / 2) + h2] = E;
}

// ---------------- K3: serial chunk combine (float2) ------------------------
__global__ __launch_bounds__(256)
void chunk_combine_kernel()
{
    int h2 = blockIdx.x * 256 + threadIdx.x;
    float2 H = make_float2(0.f, 0.f);
    for (int c = 0; c < NCH; c++) {
        size_t i = (size_t)c * (HIDN / 2) + h2;
        ((float2*)g_carry)[i] = H;
        float2 P = ((const float2*)g_P)[i];
        float2 E = ((const float2*)g_E)[i];
        H.x = P.x * H.x + E.x;  H.y = P.y * H.y + E.y;
    }
}

// ---------------- K4: re-scan with carry, y = C * h (float2) ---------------
__global__ __launch_bounds__(256)
void scan_apply_kernel()
{
    int h2 = blockIdx.y * 256 + threadIdx.x;
    int c  = blockIdx.x;
    const float2* A2 = (const float2*)g_Abar;
    const float2* B2 = (const float2*)g_Bx;
    const float2* C2 = (const float2*)g_C;
    float2* Y2 = (float2*)g_y;
    float2 H = ((const float2*)g_carry)[(size_t)c * (HIDN / 2) + h2];
    size_t base = (size_t)c * CH * (HIDN / 2) + h2;
#pragma unroll 4
    for (int i = 0; i < CH; i++) {
        size_t idx = base + (size_t)i * (HIDN / 2);
        float2 a  = A2[idx];
        float2 bx = B2[idx];
        float2 cc = C2[idx];
        H.x = a.x * H.x + bx.x;  H.y = a.y * H.y + bx.y;
        Y2[idx] = make_float2(cc.x * H.x, cc.y * H.y);
    }
}

// ---------------- K5: out = y @ W_out^T + b_out + x @ W_skip^T -------------
__global__ __launch_bounds__(256)
void out_kernel(const float* __restrict__ x,
                const float* __restrict__ Wout,
                const float* __restrict__ bout,
                const float* __restrict__ Wskip,
                float* __restrict__ out)
{
    int t  = blockIdx.x;
    int tx = threadIdx.x;
    float p[NOBJN];
#pragma unroll
    for (int j = 0; j < NOBJN; j++) p[j] = 0.f;

    const float4* y4 = (const float4*)(g_y + (size_t)t * HIDN);
#pragma unroll
    for (int it = 0; it < 2; it++) {
        int h4 = tx + it * 256;
        float4 yv = y4[h4];
#pragma unroll
        for (int j = 0; j < NOBJN; j++) {
            float4 w = ((const float4*)(Wout + (size_t)j * HIDN))[h4];
            p[j] += yv.x * w.x + yv.y * w.y + yv.z * w.z + yv.w * w.w;
        }
    }
    if (tx < 128) {
        const float4* x4 = (const float4*)(x + (size_t)t * OBSN);
        float4 xv = x4[tx];
#pragma unroll
        for (int j = 0; j < NOBJN; j++) {
            float4 w = ((const float4*)(Wskip + (size_t)j * OBSN))[tx];
            p[j] += xv.x * w.x + xv.y * w.y + xv.z * w.z + xv.w * w.w;
        }
    }

#pragma unroll
    for (int off = 16; off > 0; off >>= 1)
#pragma unroll
        for (int j = 0; j < NOBJN; j++)
            p[j] += __shfl_xor_sync(0xffffffffu, p[j], off);

    __shared__ float s[NOBJN];
    if (tx < NOBJN) s[tx] = 0.f;
    __syncthreads();
    if ((tx & 31) == 0) {
#pragma unroll
        for (int j = 0; j < NOBJN; j++)
            atomicAdd(&s[j], p[j]);
    }
    __syncthreads();
    if (tx < NOBJN)
        out[(size_t)t * NOBJN + tx] = s[tx] + bout[tx];
}

// ---------------- launch ---------------------------------------------------
extern "C" void kernel_launch(void* const* d_in, const int* in_sizes, int n_in,
                              void* d_out, int out_size)
{
    const float* x     = (const float*)d_in[0];
    const float* Win   = (const float*)d_in[1];
    const float* Wb    = (const float*)d_in[2];
    const float* Wc    = (const float*)d_in[3];
    const float* Wd    = (const float*)d_in[4];
    const float* Alog  = (const float*)d_in[5];
    const float* Wout  = (const float*)d_in[6];
    const float* bout  = (const float*)d_in[7];
    const float* Wskip = (const float*)d_in[8];
    float* out = (float*)d_out;

    __half *xh, *xl;
    cudaGetSymbolAddress((void**)&xh, g_xh);
    cudaGetSymbolAddress((void**)&xl, g_xl);

    {
        int n4 = TT * OBSN / 4;
        split_kernel<<<(n4 + 255) / 256, 256>>>(x, xh, xl, n4);
        int w4 = HIDN * OBSN / 4;
        splitw_kernel<<<dim3((w4 + 255) / 256, 4), 256>>>(Win, Wb, Wc, Wd);
    }

    cudaFuncSetAttribute(proj_mma_kernel,
                         cudaFuncAttributeMaxDynamicSharedMemorySize, PROJ_SMEM);
    dim3 g1(HIDN / PN, TT / PM);            // (64, 64)
    proj_mma_kernel<<<g1, 512, PROJ_SMEM>>>(Alog);

    chunk_scan_kernel<<<dim3(NCH, HIDN / 2 / 256), 256>>>();
    chunk_combine_kernel<<<HIDN / 2 / 256, 256>>>();
    scan_apply_kernel<<<dim3(NCH, HIDN / 2 / 256), 256>>>();

    out_kernel<<<TT, 256>>>(x, Wout, bout, Wskip, out);
}

// round 11
// speedup vs baseline: 1.5613x; 1.5613x over previous
#include <cuda_runtime.h>
#include <cuda_bf16.h>
#include <cstdint>

#define TT    8192
#define OBSN  512
#define HIDN  2048
#define NOBJN 8
#define CH    64
#define NCH   128   // TT / CH

// ---------------- scratch (device globals; no allocation allowed) ----------
__device__ float g_Abar[TT * HIDN];
__device__ float g_Bx  [TT * HIDN];
__device__ float g_C   [TT * HIDN];
__device__ float g_y   [TT * HIDN];
__device__ float g_P    [NCH * HIDN];
__device__ float g_E    [NCH * HIDN];
__device__ float g_carry[NCH * HIDN];

// tiled + pre-swizzled bf16 split copies
// x:  [64 t_blk][16 s][2 var][4096 bf16]  (8KB tile: 128 rows x 32 cols)
// W:  [64 h_blk][16 s][8 tile][1024 bf16] (2KB tile: 32 rows x 32 cols),
//      tile = var*4 + m
__device__ __nv_bfloat16 g_xt[64 * 16 * 2 * 4096];
__device__ __nv_bfloat16 g_wt[64 * 16 * 8 * 1024];

// ---------------- helpers ---------------------------------------------------
__device__ __forceinline__ uint32_t smem_u32(const void* p) {
    uint32_t a;
    asm("{ .reg .u64 t; cvta.to.shared.u64 t, %1; cvt.u32.u64 %0, t; }"
        : "=r"(a) : "l"(p));
    return a;
}

__device__ __forceinline__ void mbar_init(uint32_t a, uint32_t cnt) {
    asm volatile("mbarrier.init.shared.b64 [%0], %1;" :: "r"(a), "r"(cnt) : "memory");
}
__device__ __forceinline__ void mbar_expect_tx(uint32_t a, uint32_t bytes) {
    asm volatile("mbarrier.arrive.expect_tx.shared.b64 _, [%0], %1;"
                 :: "r"(a), "r"(bytes) : "memory");
}
__device__ __forceinline__ void mbar_wait(uint32_t a, uint32_t parity) {
    asm volatile(
        "{\n\t.reg .pred P;\n\t"
        "W_%=:\n\t"
        "mbarrier.try_wait.parity.acquire.cta.shared::cta.b64 P, [%0], %1, 0x989680;\n\t"
        "@!P bra W_%=;\n\t}"
        :: "r"(a), "r"(parity) : "memory");
}
__device__ __forceinline__ void bulk_g2s(uint32_t dst, const void* src,
                                         uint32_t bytes, uint32_t mbar) {
    asm volatile(
        "cp.async.bulk.shared::cluster.global.mbarrier::complete_tx::bytes "
        "[%0], [%1], %2, [%3];"
        :: "r"(dst), "l"(src), "r"(bytes), "r"(mbar) : "memory");
}

__device__ __forceinline__ void ldm_x4(uint32_t* r, uint32_t addr) {
    asm volatile("ldmatrix.sync.aligned.m8n8.x4.shared.b16 {%0,%1,%2,%3}, [%4];"
                 : "=r"(r[0]), "=r"(r[1]), "=r"(r[2]), "=r"(r[3]) : "r"(addr));
}

__device__ __forceinline__ void mma_bf16(float* c, const uint32_t* a,
                                         const uint32_t* b) {
    asm volatile(
        "mma.sync.aligned.m16n8k16.row.col.f32.bf16.bf16.f32 "
        "{%0,%1,%2,%3}, {%4,%5,%6,%7}, {%8,%9}, {%0,%1,%2,%3};"
        : "+f"(c[0]), "+f"(c[1]), "+f"(c[2]), "+f"(c[3])
        : "r"(a[0]), "r"(a[1]), "r"(a[2]), "r"(a[3]), "r"(b[0]), "r"(b[1]));
}

// conflict-free swizzle within a tile (64B rows)
__device__ __forceinline__ uint32_t swz(int row, int c16) {
    return (uint32_t)(row * 64 + (((c16 ^ (row >> 1)) & 3) << 4));
}

__device__ __forceinline__ uint32_t pack_hi(float a, float b) {
    __nv_bfloat162 h(__float2bfloat16(a), __float2bfloat16(b));
    return *reinterpret_cast<uint32_t*>(&h);
}
__device__ __forceinline__ uint32_t pack_lo(float a, float b) {
    float ra = a - __bfloat162float(__float2bfloat16(a));
    float rb = b - __bfloat162float(__float2bfloat16(b));
    __nv_bfloat162 h(__float2bfloat16(ra), __float2bfloat16(rb));
    return *reinterpret_cast<uint32_t*>(&h);
}

// ---------------- K0a: x -> tiled swizzled (hi, lo) ------------------------
// grid (16 s, 64 t_blk), 256 threads
__global__ __launch_bounds__(256)
void splitx_kernel(const float* __restrict__ x)
{
    int s = blockIdx.x, tb = blockIdx.y;
    size_t base = ((size_t)tb * 16 + s) * 8192;   // elements
#pragma unroll
    for (int j = 0; j < 2; j++) {
        int id = threadIdx.x + j * 256;           // 0..511
        int row = id >> 2, c16 = id & 3;
        const float* src = x + (size_t)(tb * 128 + row) * OBSN + s * 32 + c16 * 8;
        float4 v0 = *(const float4*)(src);
        float4 v1 = *(const float4*)(src + 4);
        uint4 hv, lv;
        hv.x = pack_hi(v0.x, v0.y); hv.y = pack_hi(v0.z, v0.w);
        hv.z = pack_hi(v1.x, v1.y); hv.w = pack_hi(v1.z, v1.w);
        lv.x = pack_lo(v0.x, v0.y); lv.y = pack_lo(v0.z, v0.w);
        lv.z = pack_lo(v1.x, v1.y); lv.w = pack_lo(v1.z, v1.w);
        uint32_t off = swz(row, c16);
        *(uint4*)((char*)(g_xt + base) + off)            = hv;   // hi tile
        *(uint4*)((char*)(g_xt + base + 4096) + off)     = lv;   // lo tile
    }
}

// ---------------- K0b: W -> tiled swizzled (hi tiles 0-3, lo tiles 4-7) ----
// grid (16 s, 64 h_blk), 256 threads
__global__ __launch_bounds__(256)
void splitw_kernel(const float* __restrict__ w0, const float* __restrict__ w1,
                   const float* __restrict__ w2, const float* __restrict__ w3)
{
    const float* src[4] = {w0, w1, w2, w3};
    int s = blockIdx.x, hb = blockIdx.y;
    size_t base = ((size_t)hb * 16 + s) * 8192;    // elements (16KB block)
#pragma unroll
    for (int j = 0; j < 2; j++) {
        int cid = threadIdx.x + j * 256;           // 0..511
        int m = cid >> 7, id = cid & 127;
        int row = id >> 2, c16 = id & 3;
        const float* sp = src[m] + (size_t)(hb * 32 + row) * OBSN + s * 32 + c16 * 8;
        float4 v0 = *(const float4*)(sp);
        float4 v1 = *(const float4*)(sp + 4);
        uint4 hv, lv;
        hv.x = pack_hi(v0.x, v0.y); hv.y = pack_hi(v0.z, v0.w);
        hv.z = pack_hi(v1.x, v1.y); hv.w = pack_hi(v1.z, v1.w);
        lv.x = pack_lo(v0.x, v0.y); lv.y = pack_lo(v0.z, v0.w);
        lv.z = pack_lo(v1.x, v1.y); lv.w = pack_lo(v1.z, v1.w);
        uint32_t off = swz(row, c16);
        *(uint4*)((char*)(g_wt + base + (size_t)m * 1024) + off)       = hv;
        *(uint4*)((char*)(g_wt + base + (size_t)(4 + m) * 1024) + off) = lv;
    }
}

// ---------------- K1: fused 4-projection GEMM (bf16x3, bulk-copy loads) ----
#define PM 128
#define PN 32
#define KC 32
#define NKC (OBSN / KC)           // 16
#define X_TILE_B   8192
#define W_TILE_B   2048
#define STAGE_B    32768          // [xh 8K][xl 8K][W 16K]
#define NSTAGE 3
#define MBAR_OFF   (NSTAGE * STAGE_B)      // 98304
#define PROJ_SMEM  (MBAR_OFF + 64)

// epilogue smem layout (float offsets into stage area)
#define ES    36                  // x_state stride
#define SA_F  5120                // Abar buffer (float idx), stride 33
#define SB_F  10240               // Bx buffer, stride 33
#define PE_F  15360               // seg buffer [64][4][2]

__global__ __launch_bounds__(256, 2)
void proj_mma_kernel(const float* __restrict__ Alog)
{
    extern __shared__ char smem[];
    const uint32_t sbase = smem_u32(smem);
    const int tid  = threadIdx.x;
    const int wid  = tid >> 5;
    const int lane = tid & 31;
    const int hb   = blockIdx.x;          // h block
    const int tb   = blockIdx.y;          // t block
    const int t0   = tb * PM;
    const int h0   = hb * PN;
    const int m    = wid & 3;
    const int mh   = wid >> 2;

    float acc[4][4][4];
#pragma unroll
    for (int i = 0; i < 4; i++)
#pragma unroll
        for (int j = 0; j < 4; j++)
#pragma unroll
            for (int k = 0; k < 4; k++) acc[i][j][k] = 0.f;

    if (tid == 0)
#pragma unroll
        for (int b = 0; b < NSTAGE; b++)
            mbar_init(sbase + MBAR_OFF + b * 8, 1);
    __syncthreads();

    auto issue = [&](int s) {
        if (s >= NKC || tid != 0) return;
        int b = s % NSTAGE;
        uint32_t mb = sbase + MBAR_OFF + b * 8;
        uint32_t sb = sbase + b * STAGE_B;
        mbar_expect_tx(mb, 32768u);
        bulk_g2s(sb,          g_xt + ((size_t)tb * 16 + s) * 8192, 16384u, mb);
        bulk_g2s(sb + 16384u, g_wt + ((size_t)hb * 16 + s) * 8192, 16384u, mb);
    };

    issue(0); issue(1); issue(2);

    for (int s = 0; s < NKC; s++) {
        mbar_wait(sbase + MBAR_OFF + (s % NSTAGE) * 8, (s / NSTAGE) & 1);

        const uint32_t sb   = sbase + (uint32_t)(s % NSTAGE) * STAGE_B;
        const uint32_t xh_b = sb;
        const uint32_t xl_b = sb + X_TILE_B;
        const uint32_t wh_b = sb + 2 * X_TILE_B + m * W_TILE_B;
        const uint32_t wl_b = wh_b + 4 * W_TILE_B;

#pragma unroll
        for (int ks = 0; ks < 2; ks++) {
            uint32_t ah[4][4], al[4][4], bh[4][2], bl[4][2];
#pragma unroll
            for (int mi = 0; mi < 4; mi++) {
                int row = mh * 64 + mi * 16 + (lane & 15);
                int c16 = ks * 2 + (lane >> 4);
                ldm_x4(ah[mi], xh_b + swz(row, c16));
                ldm_x4(al[mi], xl_b + swz(row, c16));
            }
#pragma unroll
            for (int np = 0; np < 2; np++) {
                int row = np * 16 + (lane & 7) + ((lane >> 4) << 3);
                int c16 = ks * 2 + ((lane >> 3) & 1);
                uint32_t r[4];
                ldm_x4(r, wh_b + swz(row, c16));
                bh[2 * np][0] = r[0]; bh[2 * np][1] = r[1];
                bh[2 * np + 1][0] = r[2]; bh[2 * np + 1][1] = r[3];
                ldm_x4(r, wl_b + swz(row, c16));
                bl[2 * np][0] = r[0]; bl[2 * np][1] = r[1];
                bl[2 * np + 1][0] = r[2]; bl[2 * np + 1][1] = r[3];
            }
#pragma unroll
            for (int mi = 0; mi < 4; mi++)
#pragma unroll
                for (int nj = 0; nj < 4; nj++) {
                    mma_bf16(acc[mi][nj], ah[mi], bh[nj]);
                    mma_bf16(acc[mi][nj], ah[mi], bl[nj]);
                    mma_bf16(acc[mi][nj], al[mi], bh[nj]);
                }
        }
        __syncthreads();        // all warps done with this stage
        issue(s + NSTAGE);      // refill same slot
    }

    // ---- epilogue: exchange x_state, compute A_bar / Bx / C + chunk (P,E) -
    float* sf = (float*)smem;
    const int rbase = mh * 64 + (lane >> 2);
    const int cbase = 2 * (lane & 3);

    if (m == 0) {   // x_state -> smem
#pragma unroll
        for (int mi = 0; mi < 4; mi++)
#pragma unroll
            for (int nj = 0; nj < 4; nj++) {
                int r = rbase + mi * 16, c = nj * 8 + cbase;
                sf[(r)     * ES + c]     = acc[mi][nj][0];
                sf[(r)     * ES + c + 1] = acc[mi][nj][1];
                sf[(r + 8) * ES + c]     = acc[mi][nj][2];
                sf[(r + 8) * ES + c + 1] = acc[mi][nj][3];
            }
    }
    if (m == 2) {   // C direct
#pragma unroll
        for (int mi = 0; mi < 4; mi++)
#pragma unroll
            for (int nj = 0; nj < 4; nj++) {
                int r = rbase + mi * 16, c = nj * 8 + cbase;
                size_t i0 = (size_t)(t0 + r) * HIDN + h0 + c;
                size_t i1 = (size_t)(t0 + r + 8) * HIDN + h0 + c;
                *(float2*)&g_C[i0] = make_float2(acc[mi][nj][0], acc[mi][nj][1]);
                *(float2*)&g_C[i1] = make_float2(acc[mi][nj][2], acc[mi][nj][3]);
            }
    }
    if (m == 3) {   // delta -> A_bar (gmem + smem)
#pragma unroll
        for (int mi = 0; mi < 4; mi++)
#pragma unroll
            for (int nj = 0; nj < 4; nj++) {
                int r = rbase + mi * 16, c = nj * 8 + cbase;
                float aA0 = -expf(__ldg(&Alog[h0 + c]));
                float aA1 = -expf(__ldg(&Alog[h0 + c + 1]));
                float d0 = 1.f / (1.f + expf(-acc[mi][nj][0]));
                float d1 = 1.f / (1.f + expf(-acc[mi][nj][1]));
                float d2 = 1.f / (1.f + expf(-acc[mi][nj][2]));
                float d3 = 1.f / (1.f + expf(-acc[mi][nj][3]));
                float a0 = expf(d0 * aA0), a1 = expf(d1 * aA1);
                float a2 = expf(d2 * aA0), a3 = expf(d3 * aA1);
                size_t i0 = (size_t)(t0 + r) * HIDN + h0 + c;
                size_t i1 = (size_t)(t0 + r + 8) * HIDN + h0 + c;
                *(float2*)&g_Abar[i0] = make_float2(a0, a1);
                *(float2*)&g_Abar[i1] = make_float2(a2, a3);
                sf[SA_F + (r)     * 33 + c]     = a0;
                sf[SA_F + (r)     * 33 + c + 1] = a1;
                sf[SA_F + (r + 8) * 33 + c]     = a2;
                sf[SA_F + (r + 8) * 33 + c + 1] = a3;
            }
    }
    __syncthreads();
    if (m == 1) {   // B * x_state (gmem + smem)
#pragma unroll
        for (int mi = 0; mi < 4; mi++)
#pragma unroll
            for (int nj = 0; nj < 4; nj++) {
                int r = rbase + mi * 16, c = nj * 8 + cbase;
                float b0 = acc[mi][nj][0] * sf[(r)     * ES + c];
                float b1 = acc[mi][nj][1] * sf[(r)     * ES + c + 1];
                float b2 = acc[mi][nj][2] * sf[(r + 8) * ES + c];
                float b3 = acc[mi][nj][3] * sf[(r + 8) * ES + c + 1];
                size_t i0 = (size_t)(t0 + r) * HIDN + h0 + c;
                size_t i1 = (size_t)(t0 + r + 8) * HIDN + h0 + c;
                *(float2*)&g_Bx[i0] = make_float2(b0, b1);
                *(float2*)&g_Bx[i1] = make_float2(b2, b3);
                sf[SB_F + (r)     * 33 + c]     = b0;
                sf[SB_F + (r)     * 33 + c + 1] = b1;
                sf[SB_F + (r + 8) * 33 + c]     = b2;
                sf[SB_F + (r + 8) * 33 + c + 1] = b3;
            }
    }
    __syncthreads();

    // ---- fused per-chunk (P, E): 64 scans (2 chunks x 32 h), 4 segs each --
    {
        int scan = tid >> 2;          // 0..63
        int seg  = tid & 3;
        int cl   = scan >> 5;         // local chunk 0/1
        int hh   = scan & 31;
        float P = 1.f, E = 0.f;
#pragma unroll 4
        for (int i = 0; i < 16; i++) {
            int r = cl * 64 + seg * 16 + i;
            float a = sf[SA_F + r * 33 + hh];
            float b = sf[SB_F + r * 33 + hh];
            E = a * E + b;
            P *= a;
        }
        sf[PE_F + (scan * 4 + seg) * 2 + 0] = P;
        sf[PE_F + (scan * 4 + seg) * 2 + 1] = E;
    }
    __syncthreads();
    if (tid < 64) {
        int cl = tid >> 5, hh = tid & 31;
        float P = 1.f, E = 0.f;
#pragma unroll
        for (int g = 0; g < 4; g++) {
            float Pg = sf[PE_F + (tid * 4 + g) * 2 + 0];
            float Eg = sf[PE_F + (tid * 4 + g) * 2 + 1];
            E = Pg * E + Eg;
            P *= Pg;
        }
        size_t idx = (size_t)(tb * 2 + cl) * HIDN + h0 + hh;
        g_P[idx] = P;
        g_E[idx] = E;
    }
}

// ---------------- K3: serial chunk combine (float2) ------------------------
__global__ __launch_bounds__(256)
void chunk_combine_kernel()
{
    int h2 = blockIdx.x * 256 + threadIdx.x;
    float2 H = make_float2(0.f, 0.f);
    for (int c = 0; c < NCH; c++) {
        size_t i = (size_t)c * (HIDN / 2) + h2;
        ((float2*)g_carry)[i] = H;
        float2 P = ((const float2*)g_P)[i];
        float2 E = ((const float2*)g_E)[i];
        H.x = P.x * H.x + E.x;  H.y = P.y * H.y + E.y;
    }
}

// ---------------- K4: re-scan with carry, y = C * h (float2) ---------------
__global__ __launch_bounds__(256)
void scan_apply_kernel()
{
    int h2 = blockIdx.y * 256 + threadIdx.x;
    int c  = blockIdx.x;
    const float2* A2 = (const float2*)g_Abar;
    const float2* B2 = (const float2*)g_Bx;
    const float2* C2 = (const float2*)g_C;
    float2* Y2 = (float2*)g_y;
    float2 H = ((const float2*)g_carry)[(size_t)c * (HIDN / 2) + h2];
    size_t base = (size_t)c * CH * (HIDN / 2) + h2;
#pragma unroll 4
    for (int i = 0; i < CH; i++) {
        size_t idx = base + (size_t)i * (HIDN / 2);
        float2 a  = A2[idx];
        float2 bx = B2[idx];
        float2 cc = C2[idx];
        H.x = a.x * H.x + bx.x;  H.y = a.y * H.y + bx.y;
        Y2[idx] = make_float2(cc.x * H.x, cc.y * H.y);
    }
}

// ---------------- K5: out = y @ W_out^T + b_out + x @ W_skip^T -------------
__global__ __launch_bounds__(256)
void out_kernel(const float* __restrict__ x,
                const float* __restrict__ Wout,
                const float* __restrict__ bout,
                const float* __restrict__ Wskip,
                float* __restrict__ out)
{
    int t  = blockIdx.x;
    int tx = threadIdx.x;
    float p[NOBJN];
#pragma unroll
    for (int j = 0; j < NOBJN; j++) p[j] = 0.f;

    const float4* y4 = (const float4*)(g_y + (size_t)t * HIDN);
#pragma unroll
    for (int it = 0; it < 2; it++) {
        int h4 = tx + it * 256;
        float4 yv = y4[h4];
#pragma unroll
        for (int j = 0; j < NOBJN; j++) {
            float4 w = ((const float4*)(Wout + (size_t)j * HIDN))[h4];
            p[j] += yv.x * w.x + yv.y * w.y + yv.z * w.z + yv.w * w.w;
        }
    }
    if (tx < 128) {
        const float4* x4 = (const float4*)(x + (size_t)t * OBSN);
        float4 xv = x4[tx];
#pragma unroll
        for (int j = 0; j < NOBJN; j++) {
            float4 w = ((const float4*)(Wskip + (size_t)j * OBSN))[tx];
            p[j] += xv.x * w.x + xv.y * w.y + xv.z * w.z + xv.w * w.w;
        }
    }

#pragma unroll
    for (int off = 16; off > 0; off >>= 1)
#pragma unroll
        for (int j = 0; j < NOBJN; j++)
            p[j] += __shfl_xor_sync(0xffffffffu, p[j], off);

    __shared__ float s[NOBJN];
    if (tx < NOBJN) s[tx] = 0.f;
    __syncthreads();
    if ((tx & 31) == 0) {
#pragma unroll
        for (int j = 0; j < NOBJN; j++)
            atomicAdd(&s[j], p[j]);
    }
    __syncthreads();
    if (tx < NOBJN)
        out[(size_t)t * NOBJN + tx] = s[tx] + bout[tx];
}

// ---------------- launch ---------------------------------------------------
extern "C" void kernel_launch(void* const* d_in, const int* in_sizes, int n_in,
                              void* d_out, int out_size)
{
    const float* x     = (const float*)d_in[0];
    const float* Win   = (const float*)d_in[1];
    const float* Wb    = (const float*)d_in[2];
    const float* Wc    = (const float*)d_in[3];
    const float* Wd    = (const float*)d_in[4];
    const float* Alog  = (const float*)d_in[5];
    const float* Wout  = (const float*)d_in[6];
    const float* bout  = (const float*)d_in[7];
    const float* Wskip = (const float*)d_in[8];
    float* out = (float*)d_out;

    splitx_kernel<<<dim3(16, 64), 256>>>(x);
    splitw_kernel<<<dim3(16, 64), 256>>>(Win, Wb, Wc, Wd);

    cudaFuncSetAttribute(proj_mma_kernel,
                         cudaFuncAttributeMaxDynamicSharedMemorySize, PROJ_SMEM);
    dim3 g1(HIDN / PN, TT / PM);            // (64, 64)
    proj_mma_kernel<<<g1, 256, PROJ_SMEM>>>(Alog);

    chunk_combine_kernel<<<HIDN / 2 / 256, 256>>>();
    scan_apply_kernel<<<dim3(NCH, HIDN / 2 / 256), 256>>>();

    out_kernel<<<TT, 256>>>(x, Wout, bout, Wskip, out);
}

// round 14
// speedup vs baseline: 1.6825x; 1.0776x over previous
#include <cuda_runtime.h>
#include <cuda_bf16.h>
#include <cstdint>

#define TT    8192
#define OBSN  512
#define HIDN  2048
#define NOBJN 8
#define CH    64
#define NCH   128   // TT / CH

// ---------------- scratch (device globals; no allocation allowed) ----------
__device__ float g_Abar[TT * HIDN];
__device__ float g_Bx  [TT * HIDN];
__device__ float g_C   [TT * HIDN];
__device__ float g_y   [TT * HIDN];
__device__ float g_P    [NCH * HIDN];
__device__ float g_E    [NCH * HIDN];
__device__ float g_carry[NCH * HIDN];

// tiled + pre-swizzled bf16 split copies
// x:  [64 t_blk][16 s][2 var][4096 bf16]  (8KB tile: 128 rows x 32 cols)
// W:  [64 h_blk][16 s][8 tile][1024 bf16] (2KB tile: 32 rows x 32 cols),
//      tile = var*4 + m
__device__ __nv_bfloat16 g_xt[64 * 16 * 2 * 4096];
__device__ __nv_bfloat16 g_wt[64 * 16 * 8 * 1024];

// ---------------- helpers ---------------------------------------------------
__device__ __forceinline__ uint32_t smem_u32(const void* p) {
    uint32_t a;
    asm("{ .reg .u64 t; cvta.to.shared.u64 t, %1; cvt.u32.u64 %0, t; }"
        : "=r"(a) : "l"(p));
    return a;
}

__device__ __forceinline__ void mbar_init(uint32_t a, uint32_t cnt) {
    asm volatile("mbarrier.init.shared.b64 [%0], %1;" :: "r"(a), "r"(cnt) : "memory");
}
__device__ __forceinline__ void mbar_expect_tx(uint32_t a, uint32_t bytes) {
    asm volatile("mbarrier.arrive.expect_tx.shared.b64 _, [%0], %1;"
                 :: "r"(a), "r"(bytes) : "memory");
}
__device__ __forceinline__ void mbar_wait(uint32_t a, uint32_t parity) {
    asm volatile(
        "{\n\t.reg .pred P;\n\t"
        "W_%=:\n\t"
        "mbarrier.try_wait.parity.acquire.cta.shared::cta.b64 P, [%0], %1, 0x989680;\n\t"
        "@!P bra W_%=;\n\t}"
        :: "r"(a), "r"(parity) : "memory");
}
__device__ __forceinline__ void bulk_g2s(uint32_t dst, const void* src,
                                         uint32_t bytes, uint32_t mbar) {
    asm volatile(
        "cp.async.bulk.shared::cluster.global.mbarrier::complete_tx::bytes "
        "[%0], [%1], %2, [%3];"
        :: "r"(dst), "l"(src), "r"(bytes), "r"(mbar) : "memory");
}

__device__ __forceinline__ void ldm_x4(uint32_t* r, uint32_t addr) {
    asm volatile("ldmatrix.sync.aligned.m8n8.x4.shared.b16 {%0,%1,%2,%3}, [%4];"
                 : "=r"(r[0]), "=r"(r[1]), "=r"(r[2]), "=r"(r[3]) : "r"(addr));
}

__device__ __forceinline__ void mma_bf16(float* c, const uint32_t* a,
                                         const uint32_t* b) {
    asm volatile(
        "mma.sync.aligned.m16n8k16.row.col.f32.bf16.bf16.f32 "
        "{%0,%1,%2,%3}, {%4,%5,%6,%7}, {%8,%9}, {%0,%1,%2,%3};"
        : "+f"(c[0]), "+f"(c[1]), "+f"(c[2]), "+f"(c[3])
        : "r"(a[0]), "r"(a[1]), "r"(a[2]), "r"(a[3]), "r"(b[0]), "r"(b[1]));
}

// conflict-free swizzle within a tile (64B rows)
__device__ __forceinline__ uint32_t swz(int row, int c16) {
    return (uint32_t)(row * 64 + (((c16 ^ (row >> 1)) & 3) << 4));
}

__device__ __forceinline__ uint32_t pack_hi(float a, float b) {
    __nv_bfloat162 h(__float2bfloat16(a), __float2bfloat16(b));
    return *reinterpret_cast<uint32_t*>(&h);
}
__device__ __forceinline__ uint32_t pack_lo(float a, float b) {
    float ra = a - __bfloat162float(__float2bfloat16(a));
    float rb = b - __bfloat162float(__float2bfloat16(b));
    __nv_bfloat162 h(__float2bfloat16(ra), __float2bfloat16(rb));
    return *reinterpret_cast<uint32_t*>(&h);
}

// ---------------- K0a: x -> tiled swizzled (hi, lo) ------------------------
// grid (16 s, 64 t_blk), 256 threads
__global__ __launch_bounds__(256)
void splitx_kernel(const float* __restrict__ x)
{
    int s = blockIdx.x, tb = blockIdx.y;
    size_t base = ((size_t)tb * 16 + s) * 8192;   // elements
#pragma unroll
    for (int j = 0; j < 2; j++) {
        int id = threadIdx.x + j * 256;           // 0..511
        int row = id >> 2, c16 = id & 3;
        const float* src = x + (size_t)(tb * 128 + row) * OBSN + s * 32 + c16 * 8;
        float4 v0 = *(const float4*)(src);
        float4 v1 = *(const float4*)(src + 4);
        uint4 hv, lv;
        hv.x = pack_hi(v0.x, v0.y); hv.y = pack_hi(v0.z, v0.w);
        hv.z = pack_hi(v1.x, v1.y); hv.w = pack_hi(v1.z, v1.w);
        lv.x = pack_lo(v0.x, v0.y); lv.y = pack_lo(v0.z, v0.w);
        lv.z = pack_lo(v1.x, v1.y); lv.w = pack_lo(v1.z, v1.w);
        uint32_t off = swz(row, c16);
        *(uint4*)((char*)(g_xt + base) + off)            = hv;   // hi tile
        *(uint4*)((char*)(g_xt + base + 4096) + off)     = lv;   // lo tile
    }
}

// ---------------- K0b: W -> tiled swizzled (hi tiles 0-3, lo tiles 4-7) ----
// grid (16 s, 64 h_blk), 256 threads
__global__ __launch_bounds__(256)
void splitw_kernel(const float* __restrict__ w0, const float* __restrict__ w1,
                   const float* __restrict__ w2, const float* __restrict__ w3)
{
    const float* src[4] = {w0, w1, w2, w3};
    int s = blockIdx.x, hb = blockIdx.y;
    size_t base = ((size_t)hb * 16 + s) * 8192;    // elements (16KB block)
#pragma unroll
    for (int j = 0; j < 2; j++) {
        int cid = threadIdx.x + j * 256;           // 0..511
        int m = cid >> 7, id = cid & 127;
        int row = id >> 2, c16 = id & 3;
        const float* sp = src[m] + (size_t)(hb * 32 + row) * OBSN + s * 32 + c16 * 8;
        float4 v0 = *(const float4*)(sp);
        float4 v1 = *(const float4*)(sp + 4);
        uint4 hv, lv;
        hv.x = pack_hi(v0.x, v0.y); hv.y = pack_hi(v0.z, v0.w);
        hv.z = pack_hi(v1.x, v1.y); hv.w = pack_hi(v1.z, v1.w);
        lv.x = pack_lo(v0.x, v0.y); lv.y = pack_lo(v0.z, v0.w);
        lv.z = pack_lo(v1.x, v1.y); lv.w = pack_lo(v1.z, v1.w);
        uint32_t off = swz(row, c16);
        *(uint4*)((char*)(g_wt + base + (size_t)m * 1024) + off)       = hv;
        *(uint4*)((char*)(g_wt + base + (size_t)(4 + m) * 1024) + off) = lv;
    }
}

// ---------------- K1: fused 4-projection GEMM (bf16x3, bulk-copy loads) ----
#define PM 128
#define PN 32
#define KC 32
#define NKC (OBSN / KC)           // 16
#define X_TILE_B   8192
#define W_TILE_B   2048
#define STAGE_B    32768          // [xh 8K][xl 8K][W 16K]
#define NSTAGE 3
#define MBAR_OFF   (NSTAGE * STAGE_B)      // 98304
#define PROJ_SMEM  (MBAR_OFF + 64)

// epilogue smem layout (float offsets into stage area)
#define ES    36                  // x_state stride
#define SA_F  5120                // Abar buffer (float idx), stride 33
#define SB_F  10240               // Bx buffer, stride 33
#define PE_F  15360               // seg buffer [64][4][2]

__global__ __launch_bounds__(256, 2)
void proj_mma_kernel(const float* __restrict__ Alog)
{
    extern __shared__ char smem[];
    const uint32_t sbase = smem_u32(smem);
    const int tid  = threadIdx.x;
    const int wid  = tid >> 5;
    const int lane = tid & 31;
    const int hb   = blockIdx.x;          // h block
    const int tb   = blockIdx.y;          // t block
    const int t0   = tb * PM;
    const int h0   = hb * PN;
    const int m    = wid & 3;
    const int mh   = wid >> 2;

    float acc[4][4][4];
#pragma unroll
    for (int i = 0; i < 4; i++)
#pragma unroll
        for (int j = 0; j < 4; j++)
#pragma unroll
            for (int k = 0; k < 4; k++) acc[i][j][k] = 0.f;

    if (tid == 0)
#pragma unroll
        for (int b = 0; b < NSTAGE; b++)
            mbar_init(sbase + MBAR_OFF + b * 8, 1);
    __syncthreads();

    auto issue = [&](int s) {
        if (s >= NKC || tid != 0) return;
        int b = s % NSTAGE;
        uint32_t mb = sbase + MBAR_OFF + b * 8;
        uint32_t sb = sbase + b * STAGE_B;
        mbar_expect_tx(mb, 32768u);
        bulk_g2s(sb,          g_xt + ((size_t)tb * 16 + s) * 8192, 16384u, mb);
        bulk_g2s(sb + 16384u, g_wt + ((size_t)hb * 16 + s) * 8192, 16384u, mb);
    };

    issue(0); issue(1); issue(2);

    for (int s = 0; s < NKC; s++) {
        mbar_wait(sbase + MBAR_OFF + (s % NSTAGE) * 8, (s / NSTAGE) & 1);

        const uint32_t sb   = sbase + (uint32_t)(s % NSTAGE) * STAGE_B;
        const uint32_t xh_b = sb;
        const uint32_t xl_b = sb + X_TILE_B;
        const uint32_t wh_b = sb + 2 * X_TILE_B + m * W_TILE_B;
        const uint32_t wl_b = wh_b + 4 * W_TILE_B;

#pragma unroll
        for (int ks = 0; ks < 2; ks++) {
            uint32_t ah[4][4], al[4][4], bh[4][2], bl[4][2];
#pragma unroll
            for (int mi = 0; mi < 4; mi++) {
                int row = mh * 64 + mi * 16 + (lane & 15);
                int c16 = ks * 2 + (lane >> 4);
                ldm_x4(ah[mi], xh_b + swz(row, c16));
                ldm_x4(al[mi], xl_b + swz(row, c16));
            }
#pragma unroll
            for (int np = 0; np < 2; np++) {
                int row = np * 16 + (lane & 7) + ((lane >> 4) << 3);
                int c16 = ks * 2 + ((lane >> 3) & 1);
                uint32_t r[4];
                ldm_x4(r, wh_b + swz(row, c16));
                bh[2 * np][0] = r[0]; bh[2 * np][1] = r[1];
                bh[2 * np + 1][0] = r[2]; bh[2 * np + 1][1] = r[3];
                ldm_x4(r, wl_b + swz(row, c16));
                bl[2 * np][0] = r[0]; bl[2 * np][1] = r[1];
                bl[2 * np + 1][0] = r[2]; bl[2 * np + 1][1] = r[3];
            }
#pragma unroll
            for (int mi = 0; mi < 4; mi++)
#pragma unroll
                for (int nj = 0; nj < 4; nj++) {
                    mma_bf16(acc[mi][nj], ah[mi], bh[nj]);
                    mma_bf16(acc[mi][nj], ah[mi], bl[nj]);
                    mma_bf16(acc[mi][nj], al[mi], bh[nj]);
                }
        }
        __syncthreads();        // all warps done with this stage
        issue(s + NSTAGE);      // refill same slot
    }

    // ---- epilogue: exchange x_state, compute A_bar / Bx / C + chunk (P,E) -
    float* sf = (float*)smem;
    const int rbase = mh * 64 + (lane >> 2);
    const int cbase = 2 * (lane & 3);

    if (m == 0) {   // x_state -> smem
#pragma unroll
        for (int mi = 0; mi < 4; mi++)
#pragma unroll
            for (int nj = 0; nj < 4; nj++) {
                int r = rbase + mi * 16, c = nj * 8 + cbase;
                sf[(r)     * ES + c]     = acc[mi][nj][0];
                sf[(r)     * ES + c + 1] = acc[mi][nj][1];
                sf[(r + 8) * ES + c]     = acc[mi][nj][2];
                sf[(r + 8) * ES + c + 1] = acc[mi][nj][3];
            }
    }
    if (m == 2) {   // C direct
#pragma unroll
        for (int mi = 0; mi < 4; mi++)
#pragma unroll
            for (int nj = 0; nj < 4; nj++) {
                int r = rbase + mi * 16, c = nj * 8 + cbase;
                size_t i0 = (size_t)(t0 + r) * HIDN + h0 + c;
                size_t i1 = (size_t)(t0 + r + 8) * HIDN + h0 + c;
                *(float2*)&g_C[i0] = make_float2(acc[mi][nj][0], acc[mi][nj][1]);
                *(float2*)&g_C[i1] = make_float2(acc[mi][nj][2], acc[mi][nj][3]);
            }
    }
    if (m == 3) {   // delta -> A_bar (gmem + smem)
#pragma unroll
        for (int mi = 0; mi < 4; mi++)
#pragma unroll
            for (int nj = 0; nj < 4; nj++) {
                int r = rbase + mi * 16, c = nj * 8 + cbase;
                float aA0 = -expf(__ldg(&Alog[h0 + c]));
                float aA1 = -expf(__ldg(&Alog[h0 + c + 1]));
                float d0 = 1.f / (1.f + expf(-acc[mi][nj][0]));
                float d1 = 1.f / (1.f + expf(-acc[mi][nj][1]));
                float d2 = 1.f / (1.f + expf(-acc[mi][nj][2]));
                float d3 = 1.f / (1.f + expf(-acc[mi][nj][3]));
                float a0 = expf(d0 * aA0), a1 = expf(d1 * aA1);
                float a2 = expf(d2 * aA0), a3 = expf(d3 * aA1);
                size_t i0 = (size_t)(t0 + r) * HIDN + h0 + c;
                size_t i1 = (size_t)(t0 + r + 8) * HIDN + h0 + c;
                *(float2*)&g_Abar[i0] = make_float2(a0, a1);
                *(float2*)&g_Abar[i1] = make_float2(a2, a3);
                sf[SA_F + (r)     * 33 + c]     = a0;
                sf[SA_F + (r)     * 33 + c + 1] = a1;
                sf[SA_F + (r + 8) * 33 + c]     = a2;
                sf[SA_F + (r + 8) * 33 + c + 1] = a3;
            }
    }
    __syncthreads();
    if (m == 1) {   // B * x_state (gmem + smem)
#pragma unroll
        for (int mi = 0; mi < 4; mi++)
#pragma unroll
            for (int nj = 0; nj < 4; nj++) {
                int r = rbase + mi * 16, c = nj * 8 + cbase;
                float b0 = acc[mi][nj][0] * sf[(r)     * ES + c];
                float b1 = acc[mi][nj][1] * sf[(r)     * ES + c + 1];
                float b2 = acc[mi][nj][2] * sf[(r + 8) * ES + c];
                float b3 = acc[mi][nj][3] * sf[(r + 8) * ES + c + 1];
                size_t i0 = (size_t)(t0 + r) * HIDN + h0 + c;
                size_t i1 = (size_t)(t0 + r + 8) * HIDN + h0 + c;
                *(float2*)&g_Bx[i0] = make_float2(b0, b1);
                *(float2*)&g_Bx[i1] = make_float2(b2, b3);
                sf[SB_F + (r)     * 33 + c]     = b0;
                sf[SB_F + (r)     * 33 + c + 1] = b1;
                sf[SB_F + (r + 8) * 33 + c]     = b2;
                sf[SB_F + (r + 8) * 33 + c + 1] = b3;
            }
    }
    __syncthreads();

    // ---- fused per-chunk (P, E): 64 scans (2 chunks x 32 h), 4 segs each --
    {
        int scan = tid >> 2;          // 0..63
        int seg  = tid & 3;
        int cl   = scan >> 5;         // local chunk 0/1
        int hh   = scan & 31;
        float P = 1.f, E = 0.f;
#pragma unroll 4
        for (int i = 0; i < 16; i++) {
            int r = cl * 64 + seg * 16 + i;
            float a = sf[SA_F + r * 33 + hh];
            float b = sf[SB_F + r * 33 + hh];
            E = a * E + b;
            P *= a;
        }
        sf[PE_F + (scan * 4 + seg) * 2 + 0] = P;
        sf[PE_F + (scan * 4 + seg) * 2 + 1] = E;
    }
    __syncthreads();
    if (tid < 64) {
        int cl = tid >> 5, hh = tid & 31;
        float P = 1.f, E = 0.f;
#pragma unroll
        for (int g = 0; g < 4; g++) {
            float Pg = sf[PE_F + (tid * 4 + g) * 2 + 0];
            float Eg = sf[PE_F + (tid * 4 + g) * 2 + 1];
            E = Pg * E + Eg;
            P *= Pg;
        }
        size_t idx = (size_t)(tb * 2 + cl) * HIDN + h0 + hh;
        g_P[idx] = P;
        g_E[idx] = E;
    }
}

// ---------------- K3: serial chunk combine, batch-prefetched ---------------
// 2048 threads (scalar per h). Per batch of 8 chunks: 16 independent loads
// first (MLP>=16), then the 8 dependent FMA+store steps.
__global__ __launch_bounds__(256)
void chunk_combine_kernel()
{
    int h = blockIdx.x * 256 + threadIdx.x;
    float H = 0.f;
    for (int c0 = 0; c0 < NCH; c0 += 8) {
        float P[8], E[8];
#pragma unroll
        for (int k = 0; k < 8; k++) {
            size_t i = (size_t)(c0 + k) * HIDN + h;
            P[k] = g_P[i];
            E[k] = g_E[i];
        }
#pragma unroll
        for (int k = 0; k < 8; k++) {
            g_carry[(size_t)(c0 + k) * HIDN + h] = H;
            H = P[k] * H + E[k];
        }
    }
}

// ---------------- K4: re-scan with carry, y = C * h (float2) ---------------
__global__ __launch_bounds__(256)
void scan_apply_kernel()
{
    int h2 = blockIdx.y * 256 + threadIdx.x;
    int c  = blockIdx.x;
    const float2* A2 = (const float2*)g_Abar;
    const float2* B2 = (const float2*)g_Bx;
    const float2* C2 = (const float2*)g_C;
    float2* Y2 = (float2*)g_y;
    float2 H = ((const float2*)g_carry)[(size_t)c * (HIDN / 2) + h2];
    size_t base = (size_t)c * CH * (HIDN / 2) + h2;
#pragma unroll 4
    for (int i = 0; i < CH; i++) {
        size_t idx = base + (size_t)i * (HIDN / 2);
        float2 a  = A2[idx];
        float2 bx = B2[idx];
        float2 cc = C2[idx];
        H.x = a.x * H.x + bx.x;  H.y = a.y * H.y + bx.y;
        Y2[idx] = make_float2(cc.x * H.x, cc.y * H.y);
    }
}

// ---------------- K5: out = y @ W_out^T + b_out + x @ W_skip^T -------------
__global__ __launch_bounds__(256)
void out_kernel(const float* __restrict__ x,
                const float* __restrict__ Wout,
                const float* __restrict__ bout,
                const float* __restrict__ Wskip,
                float* __restrict__ out)
{
    int t  = blockIdx.x;
    int tx = threadIdx.x;
    float p[NOBJN];
#pragma unroll
    for (int j = 0; j < NOBJN; j++) p[j] = 0.f;

    const float4* y4 = (const float4*)(g_y + (size_t)t * HIDN);
#pragma unroll
    for (int it = 0; it < 2; it++) {
        int h4 = tx + it * 256;
        float4 yv = y4[h4];
#pragma unroll
        for (int j = 0; j < NOBJN; j++) {
            float4 w = ((const float4*)(Wout + (size_t)j * HIDN))[h4];
            p[j] += yv.x * w.x + yv.y * w.y + yv.z * w.z + yv.w * w.w;
        }
    }
    if (tx < 128) {
        const float4* x4 = (const float4*)(x + (size_t)t * OBSN);
        float4 xv = x4[tx];
#pragma unroll
        for (int j = 0; j < NOBJN; j++) {
            float4 w = ((const float4*)(Wskip + (size_t)j * OBSN))[tx];
            p[j] += xv.x * w.x + xv.y * w.y + xv.z * w.z + xv.w * w.w;
        }
    }

#pragma unroll
    for (int off = 16; off > 0; off >>= 1)
#pragma unroll
        for (int j = 0; j < NOBJN; j++)
            p[j] += __shfl_xor_sync(0xffffffffu, p[j], off);

    __shared__ float s[NOBJN];
    if (tx < NOBJN) s[tx] = 0.f;
    __syncthreads();
    if ((tx & 31) == 0) {
#pragma unroll
        for (int j = 0; j < NOBJN; j++)
            atomicAdd(&s[j], p[j]);
    }
    __syncthreads();
    if (tx < NOBJN)
        out[(size_t)t * NOBJN + tx] = s[tx] + bout[tx];
}

// ---------------- launch ---------------------------------------------------
extern "C" void kernel_launch(void* const* d_in, const int* in_sizes, int n_in,
                              void* d_out, int out_size)
{
    const float* x     = (const float*)d_in[0];
    const float* Win   = (const float*)d_in[1];
    const float* Wb    = (const float*)d_in[2];
    const float* Wc    = (const float*)d_in[3];
    const float* Wd    = (const float*)d_in[4];
    const float* Alog  = (const float*)d_in[5];
    const float* Wout  = (const float*)d_in[6];
    const float* bout  = (const float*)d_in[7];
    const float* Wskip = (const float*)d_in[8];
    float* out = (float*)d_out;

    splitx_kernel<<<dim3(16, 64), 256>>>(x);
    splitw_kernel<<<dim3(16, 64), 256>>>(Win, Wb, Wc, Wd);

    cudaFuncSetAttribute(proj_mma_kernel,
                         cudaFuncAttributeMaxDynamicSharedMemorySize, PROJ_SMEM);
    dim3 g1(HIDN / PN, TT / PM);            // (64, 64)
    proj_mma_kernel<<<g1, 256, PROJ_SMEM>>>(Alog);

    chunk_combine_kernel<<<HIDN / 256, 256>>>();
    scan_apply_kernel<<<dim3(NCH, HIDN / 2 / 256), 256>>>();

    out_kernel<<<TT, 256>>>(x, Wout, bout, Wskip, out);
}